// round 1
// baseline (speedup 1.0000x reference)
#include <cuda_runtime.h>

// SetConv: B=4, N=2048, DX=2, DZ=128, grid 128x128 over [-2,2]^2.
// out = [x_grid (4*128*128*2 fp32) | z_grid (4*128*128*128 fp32)]

#define NPTS 2048
#define DZ   128
#define GI   128
#define GJ   128
#define TI   16
#define TJ   8
#define CH   64
#define NT   256
#define SIGMA 6.0f

#define FMA2(acc, a, bb) asm("fma.rn.f32x2 %0, %1, %2, %0;" : "+l"(acc) : "l"(a), "l"(bb))

__global__ void fill_xgrid_kernel(const float* __restrict__ grid, float* __restrict__ out) {
    int t = blockIdx.x * blockDim.x + threadIdx.x;   // float4 index within one batch copy
    if (t < (GI * GJ * 2) / 4) {
        float4 v = reinterpret_cast<const float4*>(grid)[t];
        #pragma unroll
        for (int b = 0; b < 4; ++b)
            reinterpret_cast<float4*>(out)[b * ((GI * GJ * 2) / 4) + t] = v;
    }
}

__global__ __launch_bounds__(NT, 2) void setconv_kernel(
    const float* __restrict__ x, const float* __restrict__ z,
    const float* __restrict__ grid, const float* __restrict__ lsp,
    float* __restrict__ outz)
{
    __shared__ float s_z[CH][DZ];           // 32 KB
    __shared__ float s_wx[CH][TI];          // 4 KB
    __shared__ float s_wy[CH][TJ];          // 2 KB
    __shared__ unsigned short s_list[NPTS]; // 4 KB
    __shared__ float s_px[CH], s_py[CH];
    __shared__ float s_gx[TI], s_gy[TJ];
    __shared__ int s_wcnt[8];

    const int tid  = threadIdx.x;
    const int b    = blockIdx.y;
    const int tile = blockIdx.x;            // 0..127
    const int i0 = (tile >> 4) * TI;        // 8 i-tiles
    const int j0 = (tile & 15) * TJ;        // 16 j-tiles

    const float* xb = x + (size_t)b * NPTS * 2;
    const float* zb = z + (size_t)b * NPTS * DZ;

    // lengthscale = 1e-5 + softplus(param), per dim
    float p0 = lsp[0], p1 = lsp[1];
    float l0 = 1e-5f + ((p0 > 20.f) ? p0 : log1pf(__expf(p0)));
    float l1 = 1e-5f + ((p1 > 20.f) ? p1 : log1pf(__expf(p1)));
    float invx = 0.5f / (l0 * l0);
    float invy = 0.5f / (l1 * l1);
    float Rx = SIGMA * l0, Ry = SIGMA * l1;

    if (tid < TI) s_gx[tid] = grid[(size_t)(i0 + tid) * (GJ * 2)];
    if (tid < TJ) s_gy[tid] = grid[(size_t)(j0 + tid) * 2 + 1];
    __syncthreads();

    const float xlo = s_gx[0] - Rx, xhi = s_gx[TI - 1] + Rx;
    const float ylo = s_gy[0] - Ry, yhi = s_gy[TJ - 1] + Ry;

    // ---- deterministic ordered compaction of in-range points ----
    const int lane = tid & 31, warp = tid >> 5;
    int cnt = 0;
    for (int basep = 0; basep < NPTS; basep += NT) {
        int n = basep + tid;
        float px = xb[2 * n], py = xb[2 * n + 1];
        bool ok = (px >= xlo) && (px <= xhi) && (py >= ylo) && (py <= yhi);
        unsigned mask = __ballot_sync(0xffffffffu, ok);
        if (lane == 0) s_wcnt[warp] = __popc(mask);
        __syncthreads();
        int woff = 0, tot = 0;
        #pragma unroll
        for (int w = 0; w < 8; ++w) {
            int c = s_wcnt[w];
            if (w < warp) woff += c;
            tot += c;
        }
        if (ok) s_list[cnt + woff + __popc(mask & ((1u << lane) - 1u))] = (unsigned short)n;
        cnt += tot;
        __syncthreads();
    }

    // thread microtile: 4 consecutive i rows x 16 dz
    const int dzg = tid & 7;        // 8 dz-groups of 16
    const int mg  = tid >> 3;       // 32 m-groups
    const int ig  = mg & 3;         // i-group: rows ig*4..ig*4+3
    const int jj  = mg >> 2;        // j within tile (0..7) == warp id

    unsigned long long acc[4][8];
    #pragma unroll
    for (int a = 0; a < 4; ++a)
        #pragma unroll
        for (int k = 0; k < 8; ++k) acc[a][k] = 0ull;

    // ---- main loop over accepted points in chunks ----
    for (int base = 0; base < cnt; base += CH) {
        int lim = min(CH, cnt - base);
        if (tid < lim) {
            int n = s_list[base + tid];
            s_px[tid] = xb[2 * n];
            s_py[tid] = xb[2 * n + 1];
        }
        __syncthreads();
        // separable weight tables (exp only per axis, not per pair)
        for (int e = tid; e < lim * TI; e += NT) {
            int c = e >> 4, i = e & 15;
            float d = s_gx[i] - s_px[c];
            s_wx[c][i] = __expf(-d * d * invx);
        }
        for (int e = tid; e < lim * TJ; e += NT) {
            int c = e >> 3, jq = e & 7;
            float d = s_gy[jq] - s_py[c];
            s_wy[c][jq] = __expf(-d * d * invy);
        }
        // stage z rows for the chunk
        for (int e = tid; e < lim * (DZ / 4); e += NT) {
            int c = e >> 5, q = e & 31;
            reinterpret_cast<float4*>(s_z[c])[q] =
                reinterpret_cast<const float4*>(zb + (size_t)s_list[base + c] * DZ)[q];
        }
        __syncthreads();

        for (int c = 0; c < lim; ++c) {
            float wyv = s_wy[c][jj];
            float4 wx4 = *reinterpret_cast<const float4*>(&s_wx[c][ig * 4]);
            const ulonglong2* zp = reinterpret_cast<const ulonglong2*>(&s_z[c][dzg * 16]);
            ulonglong2 q0 = zp[0], q1 = zp[1], q2 = zp[2], q3 = zp[3];
            unsigned long long zz[8] = {q0.x, q0.y, q1.x, q1.y, q2.x, q2.y, q3.x, q3.y};
            float wv[4] = {wx4.x * wyv, wx4.y * wyv, wx4.z * wyv, wx4.w * wyv};
            #pragma unroll
            for (int ii = 0; ii < 4; ++ii) {
                unsigned long long wp;
                asm("mov.b64 %0, {%1, %1};" : "=l"(wp) : "r"(__float_as_uint(wv[ii])));
                #pragma unroll
                for (int k = 0; k < 8; ++k) FMA2(acc[ii][k], wp, zz[k]);
            }
        }
        __syncthreads();
    }

    // ---- epilogue: write z_grid ----
    // z_grid flat: ((b*GI + i)*GJ + j)*DZ + d
    float* dst0 = outz +
        ((((size_t)b * GI + (i0 + ig * 4)) * GJ + (j0 + jj)) * DZ + dzg * 16);
    #pragma unroll
    for (int ii = 0; ii < 4; ++ii) {
        float* dst = dst0 + (size_t)ii * GJ * DZ;
        #pragma unroll
        for (int k = 0; k < 4; ++k) {
            ulonglong2 v;
            v.x = acc[ii][2 * k];
            v.y = acc[ii][2 * k + 1];
            reinterpret_cast<ulonglong2*>(dst)[k] = v;
        }
    }
}

extern "C" void kernel_launch(void* const* d_in, const int* in_sizes, int n_in,
                              void* d_out, int out_size) {
    (void)in_sizes; (void)n_in; (void)out_size;
    const float* x    = (const float*)d_in[0];
    const float* z    = (const float*)d_in[1];
    const float* grid = (const float*)d_in[2];
    const float* lsp  = (const float*)d_in[3];
    float* out = (float*)d_out;

    fill_xgrid_kernel<<<32, 256>>>(grid, out);                       // x_grid
    setconv_kernel<<<dim3(128, 4), NT>>>(x, z, grid, lsp,
                                         out + (size_t)4 * GI * GJ * 2);  // z_grid
}

// round 3
// speedup vs baseline: 2.8698x; 2.8698x over previous
#include <cuda_runtime.h>

// SetConv: B=4, N=2048, DX=2, DZ=128, grid 128x128 over [-2,2]^2.
// out = [x_grid (4*128*128*2 fp32) | z_grid (4*128*128*128 fp32)]

#define NPTS 2048
#define DZ   128
#define GI   128
#define GJ   128
#define TI   16
#define TJ   8
#define CH   32
#define NT   256
#define SIGMA 5.0f

#define FMA2(acc, a, bb) asm("fma.rn.f32x2 %0, %1, %2, %0;" : "+l"(acc) : "l"(a), "l"(bb))

__global__ void fill_xgrid_kernel(const float* __restrict__ grid, float* __restrict__ out) {
    int t = blockIdx.x * blockDim.x + threadIdx.x;
    if (t < (GI * GJ * 2) / 4) {
        float4 v = reinterpret_cast<const float4*>(grid)[t];
        #pragma unroll
        for (int b = 0; b < 4; ++b)
            reinterpret_cast<float4*>(out)[b * ((GI * GJ * 2) / 4) + t] = v;
    }
}

__global__ __launch_bounds__(NT, 2) void setconv_kernel(
    const float* __restrict__ x, const float* __restrict__ z,
    const float* __restrict__ grid, const float* __restrict__ lsp,
    float* __restrict__ outz)
{
    __shared__ float s_z[CH][DZ];           // 16 KB
    __shared__ float s_w[CH][TI * TJ];      // 16 KB: full weight table wx*wy
    __shared__ float s_wx[CH][TI];          // 2 KB
    __shared__ float s_wy[CH][TJ];          // 1 KB
    __shared__ unsigned short s_list[NPTS]; // 4 KB
    __shared__ float s_px[CH], s_py[CH];
    __shared__ float s_gx[TI], s_gy[TJ];
    __shared__ int s_wcnt[8];

    const int tid  = threadIdx.x;
    const int b    = blockIdx.y;
    const int tile = blockIdx.x;            // 0..127
    const int i0 = (tile >> 4) * TI;        // 8 i-tiles
    const int j0 = (tile & 15) * TJ;        // 16 j-tiles

    const float* xb = x + (size_t)b * NPTS * 2;
    const float* zb = z + (size_t)b * NPTS * DZ;

    // lengthscale = 1e-5 + softplus(param), per dim
    float p0 = lsp[0], p1 = lsp[1];
    float l0 = 1e-5f + ((p0 > 20.f) ? p0 : log1pf(__expf(p0)));
    float l1 = 1e-5f + ((p1 > 20.f) ? p1 : log1pf(__expf(p1)));
    float invx = 0.5f / (l0 * l0);
    float invy = 0.5f / (l1 * l1);
    float Rx = SIGMA * l0, Ry = SIGMA * l1;

    if (tid < TI) s_gx[tid] = grid[(size_t)(i0 + tid) * (GJ * 2)];
    if (tid < TJ) s_gy[tid] = grid[(size_t)(j0 + tid) * 2 + 1];
    __syncthreads();

    const float xlo = s_gx[0] - Rx, xhi = s_gx[TI - 1] + Rx;
    const float ylo = s_gy[0] - Ry, yhi = s_gy[TJ - 1] + Ry;

    // ---- deterministic ordered compaction of in-range points ----
    const int lane = tid & 31, warp = tid >> 5;
    int cnt = 0;
    for (int basep = 0; basep < NPTS; basep += NT) {
        int n = basep + tid;
        float px = xb[2 * n], py = xb[2 * n + 1];
        bool ok = (px >= xlo) && (px <= xhi) && (py >= ylo) && (py <= yhi);
        unsigned mask = __ballot_sync(0xffffffffu, ok);
        if (lane == 0) s_wcnt[warp] = __popc(mask);
        __syncthreads();
        int woff = 0, tot = 0;
        #pragma unroll
        for (int w = 0; w < 8; ++w) {
            int c = s_wcnt[w];
            if (w < warp) woff += c;
            tot += c;
        }
        if (ok) s_list[cnt + woff + __popc(mask & ((1u << lane) - 1u))] = (unsigned short)n;
        cnt += tot;
        __syncthreads();
    }

    // thread microtile: 8 consecutive m (fixed i, all 8 j) x 8 dz
    const int dzg  = tid & 15;      // 16 dz-groups of 8
    const int mgrp = tid >> 4;      // 16 m-groups == i row within tile

    unsigned long long acc[8][4];
    #pragma unroll
    for (int a = 0; a < 8; ++a)
        #pragma unroll
        for (int k = 0; k < 4; ++k) acc[a][k] = 0ull;

    // ---- main loop over accepted points in chunks ----
    for (int base = 0; base < cnt; base += CH) {
        int lim = min(CH, cnt - base);
        if (tid < lim) {
            int n = s_list[base + tid];
            s_px[tid] = xb[2 * n];
            s_py[tid] = xb[2 * n + 1];
        }
        __syncthreads();
        // separable exp tables
        for (int e = tid; e < lim * TI; e += NT) {
            int c = e >> 4, i = e & 15;
            float d = s_gx[i] - s_px[c];
            s_wx[c][i] = __expf(-d * d * invx);
        }
        for (int e = tid; e < lim * TJ; e += NT) {
            int c = e >> 3, jq = e & 7;
            float d = s_gy[jq] - s_py[c];
            s_wy[c][jq] = __expf(-d * d * invy);
        }
        // stage z rows for the chunk
        for (int e = tid; e < lim * (DZ / 4); e += NT) {
            int c = e >> 5, q = e & 31;
            reinterpret_cast<float4*>(s_z[c])[q] =
                reinterpret_cast<const float4*>(zb + (size_t)s_list[base + c] * DZ)[q];
        }
        __syncthreads();
        // full weight product table: w[c][m] = wx[c][i] * wy[c][j], m = i*8+j
        for (int e = tid; e < lim * (TI * TJ); e += NT) {
            int c = e >> 7, m = e & 127;
            s_w[c][m] = s_wx[c][m >> 3] * s_wy[c][m & 7];
        }
        __syncthreads();

        #pragma unroll 2
        for (int c = 0; c < lim; ++c) {
            const ulonglong2* zp = reinterpret_cast<const ulonglong2*>(&s_z[c][dzg * 8]);
            ulonglong2 za = zp[0], zb2 = zp[1];
            unsigned long long zz[4] = {za.x, za.y, zb2.x, zb2.y};
            const float4* wp = reinterpret_cast<const float4*>(&s_w[c][mgrp * 8]);
            float4 w0 = wp[0], w1 = wp[1];
            float wv[8] = {w0.x, w0.y, w0.z, w0.w, w1.x, w1.y, w1.z, w1.w};
            #pragma unroll
            for (int mm = 0; mm < 8; ++mm) {
                unsigned long long wdup;
                asm("mov.b64 %0, {%1, %1};" : "=l"(wdup) : "r"(__float_as_uint(wv[mm])));
                #pragma unroll
                for (int k = 0; k < 4; ++k) FMA2(acc[mm][k], wdup, zz[k]);
            }
        }
        __syncthreads();
    }

    // ---- epilogue: write z_grid ----
    // thread owns i = i0 + mgrp, j = j0 + mm (mm 0..7), dz = dzg*8 .. +7
    float* dst0 = outz +
        ((((size_t)b * GI + (i0 + mgrp)) * GJ + j0) * DZ + dzg * 8);
    #pragma unroll
    for (int mm = 0; mm < 8; ++mm) {
        float* dst = dst0 + (size_t)mm * DZ;
        ulonglong2 v0, v1;
        v0.x = acc[mm][0]; v0.y = acc[mm][1];
        v1.x = acc[mm][2]; v1.y = acc[mm][3];
        reinterpret_cast<ulonglong2*>(dst)[0] = v0;
        reinterpret_cast<ulonglong2*>(dst)[1] = v1;
    }
}

extern "C" void kernel_launch(void* const* d_in, const int* in_sizes, int n_in,
                              void* d_out, int out_size) {
    (void)in_sizes; (void)n_in; (void)out_size;
    const float* x    = (const float*)d_in[0];
    const float* z    = (const float*)d_in[1];
    const float* grid = (const float*)d_in[2];
    const float* lsp  = (const float*)d_in[3];
    float* out = (float*)d_out;

    fill_xgrid_kernel<<<32, 256>>>(grid, out);                           // x_grid
    setconv_kernel<<<dim3(128, 4), NT>>>(x, z, grid, lsp,
                                         out + (size_t)4 * GI * GJ * 2); // z_grid
}

// round 5
// speedup vs baseline: 6.2503x; 2.1780x over previous
#include <cuda_runtime.h>
#include <cstdint>

// SetConv via legacy mma.sync tf32 (sm_80+ path; tcgen05 unavailable at sm_103 target).
// B=4, N=2048, DZ=128, grid 128x128. out = [x_grid | z_grid] fp32.

#define NPTS 2048
#define DZ   128
#define GI   128
#define GJ   128
#define TI   16
#define TJ   8
#define NT   256
#define CH   32
#define ZPAD 136     // s_z row stride in floats -> bank = (8k+dz)%32, conflict-free
#define SIGMA 5.0f

__device__ __forceinline__ uint32_t f2tf32(float f) {
    uint32_t o;
    asm("cvt.rna.tf32.f32 %0, %1;" : "=r"(o) : "f"(f));
    return o;
}

#define MMA_TF32(d, a, b0v, b1v) \
    asm volatile("mma.sync.aligned.m16n8k8.row.col.f32.tf32.tf32.f32 " \
        "{%0,%1,%2,%3}, {%4,%5,%6,%7}, {%8,%9}, {%0,%1,%2,%3};" \
        : "+f"((d)[0]), "+f"((d)[1]), "+f"((d)[2]), "+f"((d)[3]) \
        : "r"((a)[0]), "r"((a)[1]), "r"((a)[2]), "r"((a)[3]), "r"(b0v), "r"(b1v))

__global__ void fill_xgrid_kernel(const float* __restrict__ grid, float* __restrict__ out) {
    int t = blockIdx.x * blockDim.x + threadIdx.x;
    if (t < (GI * GJ * 2) / 4) {
        float4 v = reinterpret_cast<const float4*>(grid)[t];
        #pragma unroll
        for (int b = 0; b < 4; ++b)
            reinterpret_cast<float4*>(out)[b * ((GI * GJ * 2) / 4) + t] = v;
    }
}

__global__ __launch_bounds__(NT, 2) void setconv_mma(
    const float* __restrict__ x, const float* __restrict__ z,
    const float* __restrict__ grid, const float* __restrict__ lsp,
    float* __restrict__ outz)
{
    __shared__ uint32_t s_z[CH * ZPAD];     // tf32 bits, z-transposed chunk [k][dz]
    __shared__ float s_wx[TI][36];
    __shared__ float s_wy[TJ][36];
    __shared__ unsigned short s_list[NPTS];
    __shared__ float s_px[CH], s_py[CH];
    __shared__ float s_gx[TI], s_gy[TJ];
    __shared__ int s_wcnt[8];

    const int tid  = threadIdx.x;
    const int wid  = tid >> 5, lane = tid & 31;
    const int b    = blockIdx.y;
    const int tile = blockIdx.x;
    const int i0 = (tile >> 4) * TI;
    const int j0 = (tile & 15) * TJ;

    const float* xb = x + (size_t)b * NPTS * 2;
    const float* zb = z + (size_t)b * NPTS * DZ;

    // lengthscale = 1e-5 + softplus(param)
    float p0 = lsp[0], p1 = lsp[1];
    float l0 = 1e-5f + ((p0 > 20.f) ? p0 : log1pf(__expf(p0)));
    float l1 = 1e-5f + ((p1 > 20.f) ? p1 : log1pf(__expf(p1)));
    float invx = 0.5f / (l0 * l0);
    float invy = 0.5f / (l1 * l1);
    float Rx = SIGMA * l0, Ry = SIGMA * l1;

    if (tid < TI) s_gx[tid] = grid[(size_t)(i0 + tid) * (GJ * 2)];
    if (tid < TJ) s_gy[tid] = grid[(size_t)(j0 + tid) * 2 + 1];
    __syncthreads();

    const float xlo = s_gx[0] - Rx, xhi = s_gx[TI - 1] + Rx;
    const float ylo = s_gy[0] - Ry, yhi = s_gy[TJ - 1] + Ry;

    // ---- deterministic ordered compaction ----
    int cnt = 0;
    for (int basep = 0; basep < NPTS; basep += NT) {
        int n = basep + tid;
        float px = xb[2 * n], py = xb[2 * n + 1];
        bool ok = (px >= xlo) && (px <= xhi) && (py >= ylo) && (py <= yhi);
        unsigned mask = __ballot_sync(0xffffffffu, ok);
        if (lane == 0) s_wcnt[wid] = __popc(mask);
        __syncthreads();
        int woff = 0, tot = 0;
        #pragma unroll
        for (int w = 0; w < 8; ++w) { int c = s_wcnt[w]; if (w < wid) woff += c; tot += c; }
        if (ok) s_list[cnt + woff + __popc(mask & ((1u << lane) - 1u))] = (unsigned short)n;
        cnt += tot;
        __syncthreads();
    }

    // warp tile: mh = wid>>1 selects 32 m-rows, dzh = wid&1 selects 64 dz
    const int mh  = wid >> 1;
    const int dzh = wid & 1;
    const int lq  = lane >> 2;     // groupID 0..7
    const int lr  = lane & 3;      // threadID_in_group 0..3

    float d[2][8][4];
    #pragma unroll
    for (int t = 0; t < 2; ++t)
        #pragma unroll
        for (int u = 0; u < 8; ++u)
            #pragma unroll
            for (int r = 0; r < 4; ++r) d[t][u][r] = 0.f;

    const int nch = (cnt + CH - 1) / CH;

    for (int ch = 0; ch < nch; ++ch) {
        int lim = min(CH, cnt - ch * CH);

        if (tid < CH) {
            bool v = tid < lim;
            int n = v ? s_list[ch * CH + tid] : 0;
            s_px[tid] = v ? xb[2 * n] : 1e18f;   // pad -> exp underflows to 0
            s_py[tid] = v ? xb[2 * n + 1] : 1e18f;
        }
        __syncthreads();

        // separable exp tables
        #pragma unroll
        for (int e = tid; e < TI * CH; e += NT) {
            int ii = e >> 5, c = e & 31;
            float dd = s_gx[ii] - s_px[c];
            s_wx[ii][c] = __expf(-dd * dd * invx);
        }
        if (tid < TJ * CH) {
            int jj = tid >> 5, c = tid & 31;
            float dd = s_gy[jj] - s_py[c];
            s_wy[jj][c] = __expf(-dd * dd * invy);
        }
        // stage z chunk (tf32-rounded): s_z[k][dz]
        #pragma unroll
        for (int e = tid; e < CH * (DZ / 4); e += NT) {
            int c = e >> 5, q = e & 31;
            uint4 o;
            if (c < lim) {
                const float4 v = reinterpret_cast<const float4*>(
                    zb + (size_t)s_list[ch * CH + c] * DZ)[q];
                o.x = f2tf32(v.x); o.y = f2tf32(v.y);
                o.z = f2tf32(v.z); o.w = f2tf32(v.w);
            } else {
                o.x = o.y = o.z = o.w = 0u;
            }
            *reinterpret_cast<uint4*>(&s_z[c * ZPAD + q * 4]) = o;
        }
        __syncthreads();

        #pragma unroll
        for (int ks = 0; ks < 4; ++ks) {
            const int k0 = ks * 8 + lr;
            const float wy0 = s_wy[lq][k0], wy1 = s_wy[lq][k0 + 4];
            uint32_t A[2][4];
            #pragma unroll
            for (int t = 0; t < 2; ++t) {
                const int ib = mh * 4 + 2 * t;
                A[t][0] = f2tf32(s_wx[ib][k0] * wy0);
                A[t][1] = f2tf32(s_wx[ib + 1][k0] * wy0);
                A[t][2] = f2tf32(s_wx[ib][k0 + 4] * wy1);
                A[t][3] = f2tf32(s_wx[ib + 1][k0 + 4] * wy1);
            }
            const uint32_t* zr = s_z + k0 * ZPAD + dzh * 64 + lq;
            #pragma unroll
            for (int u = 0; u < 8; ++u) {
                uint32_t b0 = zr[u * 8];
                uint32_t b1 = zr[4 * ZPAD + u * 8];
                MMA_TF32(d[0][u], A[0], b0, b1);
                MMA_TF32(d[1][u], A[1], b0, b1);
            }
        }
        __syncthreads();
    }

    // ---- epilogue ----
    // lane owns rows m = mh*32 + t*16 + lq (+8), cols dz = dzh*64 + u*8 + 2*lr (+1)
    #pragma unroll
    for (int t = 0; t < 2; ++t) {
        const int m0 = mh * 32 + t * 16 + lq;
        #pragma unroll
        for (int h = 0; h < 2; ++h) {
            const int m = m0 + h * 8;
            const int gi = i0 + (m >> 3), gj = j0 + (m & 7);
            float* dst = outz + (((size_t)b * GI + gi) * GJ + gj) * DZ
                       + dzh * 64 + 2 * lr;
            #pragma unroll
            for (int u = 0; u < 8; ++u) {
                float2 v;
                v.x = d[t][u][2 * h];
                v.y = d[t][u][2 * h + 1];
                *reinterpret_cast<float2*>(dst + u * 8) = v;
            }
        }
    }
}

extern "C" void kernel_launch(void* const* d_in, const int* in_sizes, int n_in,
                              void* d_out, int out_size) {
    (void)in_sizes; (void)n_in; (void)out_size;
    const float* x    = (const float*)d_in[0];
    const float* z    = (const float*)d_in[1];
    const float* grid = (const float*)d_in[2];
    const float* lsp  = (const float*)d_in[3];
    float* out = (float*)d_out;

    fill_xgrid_kernel<<<32, 256>>>(grid, out);
    setconv_mma<<<dim3(128, 4), NT>>>(x, z, grid, lsp,
                                      out + (size_t)4 * GI * GJ * 2);
}

// round 7
// speedup vs baseline: 8.6658x; 1.3865x over previous
#include <cuda_runtime.h>
#include <cstdint>

// SetConv via legacy mma.sync tf32 + cp.async double-buffered staging.
// B=4, N=2048, DZ=128, grid 128x128. out = [x_grid | z_grid] fp32.

#define NPTS 2048
#define DZ   128
#define GI   128
#define GJ   128
#define TI   16
#define TJ   8
#define NT   256
#define CH   32
#define ZPAD 136                 // floats per z row in smem (conflict-free)
#define ZROWB (ZPAD * 4)         // 544 bytes
#define ZBUFB (CH * ZROWB)       // 17408 bytes per buffer
#define SIGMA 5.0f

__device__ __forceinline__ uint32_t f2tf32(float f) {
    uint32_t o;
    asm("cvt.rna.tf32.f32 %0, %1;" : "=r"(o) : "f"(f));
    return o;
}
__device__ __forceinline__ uint32_t s2u(const void* p) {
    uint32_t a;
    asm("{ .reg .u64 t; cvta.to.shared.u64 t, %1; cvt.u32.u64 %0, t; }" : "=r"(a) : "l"(p));
    return a;
}
__device__ __forceinline__ void cpasync16(uint32_t dst, const void* src) {
    asm volatile("cp.async.cg.shared.global [%0], [%1], 16;" :: "r"(dst), "l"(src));
}

#define MMA_TF32(d, a, b0v, b1v) \
    asm volatile("mma.sync.aligned.m16n8k8.row.col.f32.tf32.tf32.f32 " \
        "{%0,%1,%2,%3}, {%4,%5,%6,%7}, {%8,%9}, {%0,%1,%2,%3};" \
        : "+f"((d)[0]), "+f"((d)[1]), "+f"((d)[2]), "+f"((d)[3]) \
        : "r"((a)[0]), "r"((a)[1]), "r"((a)[2]), "r"((a)[3]), "r"(b0v), "r"(b1v))

__global__ __launch_bounds__(NT, 2) void setconv_mma(
    const float* __restrict__ x, const float* __restrict__ z,
    const float* __restrict__ grid, const float* __restrict__ lsp,
    float* __restrict__ out)
{
    extern __shared__ char dyn[];
    float*          zbuf = reinterpret_cast<float*>(dyn);            // [2][CH][ZPAD]
    float2*         pall = reinterpret_cast<float2*>(dyn + 2 * ZBUFB);
    unsigned short* list = reinterpret_cast<unsigned short*>(dyn + 2 * ZBUFB + NPTS * 8);

    __shared__ float s_wx[TI][36];
    __shared__ float s_wy[TJ][36];
    __shared__ float s_gx[TI], s_gy[TJ];
    __shared__ int s_wcnt[8];

    const int tid  = threadIdx.x;
    const int wid  = tid >> 5, lane = tid & 31;
    const int b    = blockIdx.y;
    const int tile = blockIdx.x;
    const int i0 = (tile >> 4) * TI;
    const int j0 = (tile & 15) * TJ;

    const float* xb = x + (size_t)b * NPTS * 2;
    const float* zb = z + (size_t)b * NPTS * DZ;
    float* outz = out + (size_t)4 * GI * GJ * 2;

    // x_grid: each block writes its own tile cells for its batch
    if (tid < TI * TJ) {
        int ii = tid >> 3, jj = tid & 7;
        float2 g = reinterpret_cast<const float2*>(grid)[(i0 + ii) * GJ + (j0 + jj)];
        reinterpret_cast<float2*>(out)[((size_t)b * GI + i0 + ii) * GJ + (j0 + jj)] = g;
    }

    // lengthscale = 1e-5 + softplus(param)
    float p0 = lsp[0], p1 = lsp[1];
    float l0 = 1e-5f + ((p0 > 20.f) ? p0 : log1pf(__expf(p0)));
    float l1 = 1e-5f + ((p1 > 20.f) ? p1 : log1pf(__expf(p1)));
    float invx = 0.5f / (l0 * l0);
    float invy = 0.5f / (l1 * l1);
    float Rx = SIGMA * l0, Ry = SIGMA * l1;

    if (tid < TI) s_gx[tid] = grid[(size_t)(i0 + tid) * (GJ * 2)];
    if (tid < TJ) s_gy[tid] = grid[(size_t)(j0 + tid) * 2 + 1];
    __syncthreads();

    const float xlo = s_gx[0] - Rx, xhi = s_gx[TI - 1] + Rx;
    const float ylo = s_gy[0] - Ry, yhi = s_gy[TJ - 1] + Ry;

    // ---- 2-barrier deterministic compaction (warp w owns span [w*256, w*256+256)) ----
    float pxr[8], pyr[8];
    unsigned okm[8];
    int myCnt = 0;
    #pragma unroll
    for (int r = 0; r < 8; ++r) {
        int n = (wid << 8) + (r << 5) + lane;
        float px = xb[2 * n], py = xb[2 * n + 1];
        bool ok = (px >= xlo) && (px <= xhi) && (py >= ylo) && (py <= yhi);
        okm[r] = __ballot_sync(0xffffffffu, ok);
        pxr[r] = px; pyr[r] = py;
        myCnt += __popc(okm[r]);
    }
    if (lane == 0) s_wcnt[wid] = myCnt;
    __syncthreads();
    int cnt = 0, basew = 0;
    #pragma unroll
    for (int w = 0; w < 8; ++w) {
        int c = s_wcnt[w];
        if (w < wid) basew += c;
        cnt += c;
    }
    {
        int pos = basew;
        #pragma unroll
        for (int r = 0; r < 8; ++r) {
            unsigned mask = okm[r];
            bool ok = (mask >> lane) & 1u;
            int idx = pos + __popc(mask & ((1u << lane) - 1u));
            if (ok) {
                list[idx] = (unsigned short)((wid << 8) + (r << 5) + lane);
                pall[idx] = make_float2(pxr[r], pyr[r]);
            }
            pos += __popc(mask);
        }
    }
    __syncthreads();

    const int nch = (cnt > 0) ? ((cnt + CH - 1) / CH) : 1;
    const uint32_t zbase = s2u(dyn);

    // issue cp.async staging for chunk ch into buffer p
    auto issue_z = [&](int ch, int p) {
        #pragma unroll
        for (int k = 0; k < 4; ++k) {
            int u = tid + k * NT;            // 0..1023
            int c = u >> 5, s = u & 31;      // row, 16B unit
            int gi_ = ch * CH + c;
            uint32_t dst = zbase + (uint32_t)(p * ZBUFB + c * ZROWB + s * 16);
            if (gi_ < cnt) {
                cpasync16(dst, reinterpret_cast<const char*>(zb) +
                               (size_t)list[gi_] * (DZ * 4) + s * 16);
            } else {
                *reinterpret_cast<uint4*>(dyn + p * ZBUFB + c * ZROWB + s * 16) =
                    make_uint4(0u, 0u, 0u, 0u);
            }
        }
        asm volatile("cp.async.commit_group;" ::: "memory");
    };

    issue_z(0, 0);

    // warp tile: mh selects 32 m-rows, dzh selects 64 dz
    const int mh  = wid >> 1;
    const int dzh = wid & 1;
    const int lq  = lane >> 2;
    const int lr  = lane & 3;

    float d[2][8][4];
    #pragma unroll
    for (int t = 0; t < 2; ++t)
        #pragma unroll
        for (int u = 0; u < 8; ++u)
            #pragma unroll
            for (int r = 0; r < 4; ++r) d[t][u][r] = 0.f;

    for (int ch = 0; ch < nch; ++ch) {
        const int p = ch & 1;
        if (ch + 1 < nch) issue_z(ch + 1, p ^ 1);

        // separable exp tables for this chunk (pad -> huge dist -> exp = 0)
        #pragma unroll
        for (int e = tid; e < TI * CH; e += NT) {
            int ii = e >> 5, c = e & 31, idx = ch * CH + c;
            float px = (idx < cnt) ? pall[idx].x : 1e18f;
            float dd = s_gx[ii] - px;
            s_wx[ii][c] = __expf(-dd * dd * invx);
        }
        if (tid < TJ * CH) {
            int jj = tid >> 5, c = tid & 31, idx = ch * CH + c;
            float py = (idx < cnt) ? pall[idx].y : 1e18f;
            float dd = s_gy[jj] - py;
            s_wy[jj][c] = __expf(-dd * dd * invy);
        }

        if (ch + 1 < nch) asm volatile("cp.async.wait_group 1;" ::: "memory");
        else              asm volatile("cp.async.wait_group 0;" ::: "memory");
        __syncthreads();

        const uint32_t* zbp = reinterpret_cast<const uint32_t*>(dyn + p * ZBUFB);
        #pragma unroll
        for (int ks = 0; ks < 4; ++ks) {
            const int k0 = ks * 8 + lr;
            const float wy0 = s_wy[lq][k0], wy1 = s_wy[lq][k0 + 4];
            uint32_t A[2][4];
            #pragma unroll
            for (int t = 0; t < 2; ++t) {
                const int ib = mh * 4 + 2 * t;
                A[t][0] = f2tf32(s_wx[ib][k0] * wy0);
                A[t][1] = f2tf32(s_wx[ib + 1][k0] * wy0);
                A[t][2] = f2tf32(s_wx[ib][k0 + 4] * wy1);
                A[t][3] = f2tf32(s_wx[ib + 1][k0 + 4] * wy1);
            }
            const uint32_t* zr = zbp + k0 * ZPAD + dzh * 64 + lq;
            #pragma unroll
            for (int u = 0; u < 8; ++u) {
                uint32_t b0 = zr[u * 8];
                uint32_t b1 = zr[4 * ZPAD + u * 8];
                MMA_TF32(d[0][u], A[0], b0, b1);
                MMA_TF32(d[1][u], A[1], b0, b1);
            }
        }
        __syncthreads();
    }

    // ---- epilogue ----
    #pragma unroll
    for (int t = 0; t < 2; ++t) {
        const int m0 = mh * 32 + t * 16 + lq;
        #pragma unroll
        for (int h = 0; h < 2; ++h) {
            const int m = m0 + h * 8;
            const int gi = i0 + (m >> 3), gj = j0 + (m & 7);
            float* dst = outz + (((size_t)b * GI + gi) * GJ + gj) * DZ
                       + dzh * 64 + 2 * lr;
            #pragma unroll
            for (int u = 0; u < 8; ++u) {
                float2 v;
                v.x = d[t][u][2 * h];
                v.y = d[t][u][2 * h + 1];
                *reinterpret_cast<float2*>(dst + u * 8) = v;
            }
        }
    }
}

extern "C" void kernel_launch(void* const* d_in, const int* in_sizes, int n_in,
                              void* d_out, int out_size) {
    (void)in_sizes; (void)n_in; (void)out_size;
    const float* x    = (const float*)d_in[0];
    const float* z    = (const float*)d_in[1];
    const float* grid = (const float*)d_in[2];
    const float* lsp  = (const float*)d_in[3];
    float* out = (float*)d_out;

    const int dyn_bytes = 2 * ZBUFB + NPTS * 8 + NPTS * 2;  // zbufs + pall + list
    cudaFuncSetAttribute((const void*)setconv_mma,
                         cudaFuncAttributeMaxDynamicSharedMemorySize, dyn_bytes);

    setconv_mma<<<dim3(128, 4), NT, dyn_bytes>>>(x, z, grid, lsp, out);
}

// round 8
// speedup vs baseline: 9.1108x; 1.0514x over previous
#include <cuda_runtime.h>
#include <cstdint>

// SetConv via mma.sync tf32, cp.async triple-buffered z staging, 1 barrier/chunk.
// B=4, N=2048, DZ=128, grid 128x128. out = [x_grid | z_grid] fp32.

#define NPTS 2048
#define DZ   128
#define GI   128
#define GJ   128
#define TI   16
#define TJ   8
#define NT   256
#define CH   32
#define ZPAD 136                 // floats per z row in smem (conflict-free)
#define ZROWB (ZPAD * 4)         // 544 bytes
#define ZBUFB (CH * ZROWB)       // 17408 bytes per buffer
#define NZBUF 3
#define SIGMA 4.0f

__device__ __forceinline__ uint32_t f2tf32(float f) {
    uint32_t o;
    asm("cvt.rna.tf32.f32 %0, %1;" : "=r"(o) : "f"(f));
    return o;
}
__device__ __forceinline__ uint32_t s2u(const void* p) {
    uint32_t a;
    asm("{ .reg .u64 t; cvta.to.shared.u64 t, %1; cvt.u32.u64 %0, t; }" : "=r"(a) : "l"(p));
    return a;
}
__device__ __forceinline__ void cpasync16(uint32_t dst, const void* src) {
    asm volatile("cp.async.cg.shared.global [%0], [%1], 16;" :: "r"(dst), "l"(src));
}

#define MMA_TF32(d, a, b0v, b1v) \
    asm volatile("mma.sync.aligned.m16n8k8.row.col.f32.tf32.tf32.f32 " \
        "{%0,%1,%2,%3}, {%4,%5,%6,%7}, {%8,%9}, {%0,%1,%2,%3};" \
        : "+f"((d)[0]), "+f"((d)[1]), "+f"((d)[2]), "+f"((d)[3]) \
        : "r"((a)[0]), "r"((a)[1]), "r"((a)[2]), "r"((a)[3]), "r"(b0v), "r"(b1v))

__global__ __launch_bounds__(NT, 2) void setconv_mma(
    const float* __restrict__ x, const float* __restrict__ z,
    const float* __restrict__ grid, const float* __restrict__ lsp,
    float* __restrict__ out)
{
    extern __shared__ char dyn[];
    float2*         pall = reinterpret_cast<float2*>(dyn + NZBUF * ZBUFB);
    unsigned short* list = reinterpret_cast<unsigned short*>(dyn + NZBUF * ZBUFB + NPTS * 8);

    __shared__ float s_wx[2][TI][36];
    __shared__ float s_wy[2][TJ][36];
    __shared__ float s_gx[TI], s_gy[TJ];
    __shared__ int s_wcnt[8];

    const int tid  = threadIdx.x;
    const int wid  = tid >> 5, lane = tid & 31;
    const int b    = blockIdx.y;
    const int tile = blockIdx.x;
    const int i0 = (tile >> 4) * TI;
    const int j0 = (tile & 15) * TJ;

    const float* xb = x + (size_t)b * NPTS * 2;
    const float* zb = z + (size_t)b * NPTS * DZ;
    float* outz = out + (size_t)4 * GI * GJ * 2;

    // x_grid: each block writes its own tile cells for its batch
    if (tid < TI * TJ) {
        int ii = tid >> 3, jj = tid & 7;
        float2 g = reinterpret_cast<const float2*>(grid)[(i0 + ii) * GJ + (j0 + jj)];
        reinterpret_cast<float2*>(out)[((size_t)b * GI + i0 + ii) * GJ + (j0 + jj)] = g;
    }

    // lengthscale = 1e-5 + softplus(param)
    float p0 = lsp[0], p1 = lsp[1];
    float l0 = 1e-5f + ((p0 > 20.f) ? p0 : log1pf(__expf(p0)));
    float l1 = 1e-5f + ((p1 > 20.f) ? p1 : log1pf(__expf(p1)));
    float invx = 0.5f / (l0 * l0);
    float invy = 0.5f / (l1 * l1);
    float Rx = SIGMA * l0, Ry = SIGMA * l1;

    if (tid < TI) s_gx[tid] = grid[(size_t)(i0 + tid) * (GJ * 2)];
    if (tid < TJ) s_gy[tid] = grid[(size_t)(j0 + tid) * 2 + 1];
    __syncthreads();

    const float xlo = s_gx[0] - Rx, xhi = s_gx[TI - 1] + Rx;
    const float ylo = s_gy[0] - Ry, yhi = s_gy[TJ - 1] + Ry;

    // ---- 2-barrier deterministic compaction ----
    float pxr[8], pyr[8];
    unsigned okm[8];
    int myCnt = 0;
    #pragma unroll
    for (int r = 0; r < 8; ++r) {
        int n = (wid << 8) + (r << 5) + lane;
        float px = xb[2 * n], py = xb[2 * n + 1];
        bool ok = (px >= xlo) && (px <= xhi) && (py >= ylo) && (py <= yhi);
        okm[r] = __ballot_sync(0xffffffffu, ok);
        pxr[r] = px; pyr[r] = py;
        myCnt += __popc(okm[r]);
    }
    if (lane == 0) s_wcnt[wid] = myCnt;
    __syncthreads();
    int cnt = 0, basew = 0;
    #pragma unroll
    for (int w = 0; w < 8; ++w) {
        int c = s_wcnt[w];
        if (w < wid) basew += c;
        cnt += c;
    }
    {
        int pos = basew;
        #pragma unroll
        for (int r = 0; r < 8; ++r) {
            unsigned mask = okm[r];
            bool ok = (mask >> lane) & 1u;
            int idx = pos + __popc(mask & ((1u << lane) - 1u));
            if (ok) {
                list[idx] = (unsigned short)((wid << 8) + (r << 5) + lane);
                pall[idx] = make_float2(pxr[r], pyr[r]);
            }
            pos += __popc(mask);
        }
    }
    __syncthreads();

    const int nch = (cnt > 0) ? ((cnt + CH - 1) / CH) : 1;
    const uint32_t zbase = s2u(dyn);

    auto issue_z = [&](int ch, int p) {
        #pragma unroll
        for (int k = 0; k < 4; ++k) {
            int u = tid + k * NT;            // 0..1023
            int c = u >> 5, s = u & 31;      // row, 16B unit
            int gi_ = ch * CH + c;
            if (gi_ < cnt) {
                cpasync16(zbase + (uint32_t)(p * ZBUFB + c * ZROWB + s * 16),
                          reinterpret_cast<const char*>(zb) +
                          (size_t)list[gi_] * (DZ * 4) + s * 16);
            } else {
                *reinterpret_cast<uint4*>(dyn + p * ZBUFB + c * ZROWB + s * 16) =
                    make_uint4(0u, 0u, 0u, 0u);
            }
        }
        asm volatile("cp.async.commit_group;" ::: "memory");
    };

    issue_z(0, 0);

    // warp tile: 64 m-rows x 32 dz
    const int mh  = wid & 1;       // m half
    const int dzq = wid >> 1;      // dz quarter (0..3)
    const int lq  = lane >> 2;
    const int lr  = lane & 3;

    float d[4][4][4];
    #pragma unroll
    for (int t = 0; t < 4; ++t)
        #pragma unroll
        for (int u = 0; u < 4; ++u)
            #pragma unroll
            for (int r = 0; r < 4; ++r) d[t][u][r] = 0.f;

    for (int ch = 0; ch < nch; ++ch) {
        const int p  = ch % NZBUF;
        const int tb = ch & 1;
        if (ch + 1 < nch) issue_z(ch + 1, (ch + 1) % NZBUF);

        // separable exp tables for this chunk (pad -> huge dist -> exp = 0)
        #pragma unroll
        for (int e = tid; e < TI * CH; e += NT) {
            int ii = e >> 5, c = e & 31, idx = ch * CH + c;
            float px = (idx < cnt) ? pall[idx].x : 1e18f;
            float dd = s_gx[ii] - px;
            s_wx[tb][ii][c] = __expf(-dd * dd * invx);
        }
        if (tid < TJ * CH) {
            int jj = tid >> 5, c = tid & 31, idx = ch * CH + c;
            float py = (idx < cnt) ? pall[idx].y : 1e18f;
            float dd = s_gy[jj] - py;
            s_wy[tb][jj][c] = __expf(-dd * dd * invy);
        }

        if (ch + 1 < nch) asm volatile("cp.async.wait_group 1;" ::: "memory");
        else              asm volatile("cp.async.wait_group 0;" ::: "memory");
        __syncthreads();   // single barrier per chunk

        const uint32_t* zbp = reinterpret_cast<const uint32_t*>(dyn + p * ZBUFB);
        #pragma unroll
        for (int ks = 0; ks < 4; ++ks) {
            const int k0 = ks * 8 + lr;
            const float wy0 = s_wy[tb][lq][k0], wy1 = s_wy[tb][lq][k0 + 4];
            uint32_t A[4][4];
            #pragma unroll
            for (int t = 0; t < 4; ++t) {
                const int ib = mh * 8 + 2 * t;
                A[t][0] = f2tf32(s_wx[tb][ib][k0] * wy0);
                A[t][1] = f2tf32(s_wx[tb][ib + 1][k0] * wy0);
                A[t][2] = f2tf32(s_wx[tb][ib][k0 + 4] * wy1);
                A[t][3] = f2tf32(s_wx[tb][ib + 1][k0 + 4] * wy1);
            }
            const uint32_t* zr = zbp + k0 * ZPAD + dzq * 32 + lq;
            #pragma unroll
            for (int u = 0; u < 4; ++u) {
                // +0x1000: round-half-up to tf32 instead of HW truncation
                uint32_t b0 = zr[u * 8] + 0x1000u;
                uint32_t b1 = zr[4 * ZPAD + u * 8] + 0x1000u;
                #pragma unroll
                for (int t = 0; t < 4; ++t) MMA_TF32(d[t][u], A[t], b0, b1);
            }
        }
    }

    // ---- epilogue ----
    // lane owns rows m = mh*64 + t*16 + h*8 + lq; cols dz = dzq*32 + u*8 + 2*lr(+1)
    #pragma unroll
    for (int t = 0; t < 4; ++t) {
        #pragma unroll
        for (int h = 0; h < 2; ++h) {
            const int m = mh * 64 + t * 16 + h * 8 + lq;
            const int gi = i0 + (m >> 3), gj = j0 + (m & 7);
            float* dst = outz + (((size_t)b * GI + gi) * GJ + gj) * DZ
                       + dzq * 32 + 2 * lr;
            #pragma unroll
            for (int u = 0; u < 4; ++u) {
                float2 v;
                v.x = d[t][u][2 * h];
                v.y = d[t][u][2 * h + 1];
                *reinterpret_cast<float2*>(dst + u * 8) = v;
            }
        }
    }
}

extern "C" void kernel_launch(void* const* d_in, const int* in_sizes, int n_in,
                              void* d_out, int out_size) {
    (void)in_sizes; (void)n_in; (void)out_size;
    const float* x    = (const float*)d_in[0];
    const float* z    = (const float*)d_in[1];
    const float* grid = (const float*)d_in[2];
    const float* lsp  = (const float*)d_in[3];
    float* out = (float*)d_out;

    const int dyn_bytes = NZBUF * ZBUFB + NPTS * 8 + NPTS * 2;  // zbufs + pall + list
    cudaFuncSetAttribute((const void*)setconv_mma,
                         cudaFuncAttributeMaxDynamicSharedMemorySize, dyn_bytes);

    setconv_mma<<<dim3(128, 4), NT, dyn_bytes>>>(x, z, grid, lsp, out);
}